// round 11
// baseline (speedup 1.0000x reference)
#include <cuda_runtime.h>
#include <cuda_bf16.h>
#include <cstdint>

// ---------------------------------------------------------------------------
// Reading_memory R9: mma.sync bf16x3 GEMMs; 4m x 2n warp layout (2 m-tiles
// per warp -> 2x B-fragment reuse), A register-direct, B cp.async dbl-buffer.
// ---------------------------------------------------------------------------

#define B_MAX 65536
#define HID 100
#define MT   128
#define KCH  64
#define ASTB 72                    // B image k-stride (elems)
#define BSPL (104 * ASTB * 2)      // bytes per split
#define BCHK (2 * BSPL)
typedef unsigned long long ull;
typedef unsigned int uint;

__device__ __align__(16) static float g_m4[B_MAX * 500];
__device__ __align__(16) static float g_s4[B_MAX * 500];
__device__ __align__(16) static float g_sm[B_MAX * 500];
__device__ __align__(16) static __nv_bfloat16 g_Bimg[11][2][104 * ASTB];

__device__ __forceinline__ float sigf(float x) { return 1.0f / (1.0f + __expf(-x)); }

__device__ __forceinline__ ull fma2(ull a, ull b, ull c) {
    ull d;
    asm("fma.rn.f32x2 %0, %1, %2, %3;" : "=l"(d) : "l"(a), "l"(b), "l"(c));
    return d;
}
__device__ __forceinline__ ull pack2(float lo, float hi) {
    ull r;
    asm("mov.b64 %0, {%1, %2};" : "=l"(r) : "r"(__float_as_uint(lo)), "r"(__float_as_uint(hi)));
    return r;
}
__device__ __forceinline__ float2 unpack2(ull v) {
    uint lo, hi;
    asm("mov.b64 {%0, %1}, %2;" : "=r"(lo), "=r"(hi) : "l"(v));
    float2 r; r.x = __uint_as_float(lo); r.y = __uint_as_float(hi);
    return r;
}
__device__ __forceinline__ void sp2(float2 v, uint& h, uint& l) {
    uint hh;
    asm("cvt.rn.bf16x2.f32 %0, %1, %2;" : "=r"(hh) : "f"(v.y), "f"(v.x));
    float rx = v.x - __uint_as_float(hh << 16);
    float ry = v.y - __uint_as_float(hh & 0xFFFF0000u);
    asm("cvt.rn.bf16x2.f32 %0, %1, %2;" : "=r"(l) : "f"(ry), "f"(rx));
    h = hh;
}

#define LDSM2(d0, d1, addr) \
    asm volatile("ldmatrix.sync.aligned.m8n8.x2.shared.b16 {%0,%1}, [%2];" \
                 : "=r"(d0), "=r"(d1) : "r"(addr))
#define LDSM4(d0, d1, d2, d3, addr) \
    asm volatile("ldmatrix.sync.aligned.m8n8.x4.shared.b16 {%0,%1,%2,%3}, [%4];" \
                 : "=r"(d0), "=r"(d1), "=r"(d2), "=r"(d3) : "r"(addr))

__device__ __forceinline__ void mma16816(float c[4], const uint a[4], uint b0, uint b1) {
    asm volatile(
        "mma.sync.aligned.m16n8k16.row.col.f32.bf16.bf16.f32 "
        "{%0,%1,%2,%3}, {%4,%5,%6,%7}, {%8,%9}, {%0,%1,%2,%3};"
        : "+f"(c[0]), "+f"(c[1]), "+f"(c[2]), "+f"(c[3])
        : "r"(a[0]), "r"(a[1]), "r"(a[2]), "r"(a[3]), "r"(b0), "r"(b1));
}

__device__ __forceinline__ void cpa16(uint saddr, const void* src) {
    asm volatile("cp.async.cg.shared.global [%0], [%1], 16;" :: "r"(saddr), "l"(src));
}

// ---------------------------------------------------------------------------
__global__ void prep_kernel(const float* __restrict__ Wm,
                            const float* __restrict__ Ws,
                            const float* __restrict__ Wg)
{
    const int idx = blockIdx.x * blockDim.x + threadIdx.x;
    const int PER = 104 * KCH;
    if (idx >= 11 * PER) return;
    const int cidx = idx / PER;
    const int rem = idx - cidx * PER;
    const int n = rem / KCH, k = rem - n * KCH;
    int c, KS;
    const float* W;
    if (cidx < 2)      { W = Wm; c = cidx;     KS = 100; }
    else if (cidx < 6) { W = Ws; c = cidx - 2; KS = 200; }
    else               { W = Wg; c = cidx - 6; KS = 300; }
    const int gk = c * KCH + k;
    float v = (n < HID && gk < KS) ? W[gk * HID + n] : 0.0f;
    __nv_bfloat16 hi = __float2bfloat16(v);
    __nv_bfloat16 lo = __float2bfloat16(v - __bfloat162float(hi));
    g_Bimg[cidx][0][n * ASTB + k] = hi;
    g_Bimg[cidx][1][n * ASTB + k] = lo;
}

// ---------------------------------------------------------------------------
#define OFF_BIAS (2 * BCHK)
#define GSMEM (OFF_BIAS + 104 * 4)

template <int STAGE>
__device__ __forceinline__ float2 ldx(const float* __restrict__ se,
                                      const float* __restrict__ mem,
                                      const float* __restrict__ raw,
                                      int grow, int k, int rows)
{
    constexpr int KS = (STAGE == 0) ? 100 : (STAGE == 1 ? 200 : 300);
    float2 z = make_float2(0.f, 0.f);
    if (grow >= rows || k >= KS) return z;
    if (STAGE == 0) return *(const float2*)&mem[grow * HID + k];
    if (STAGE == 1) {
        return (k < HID) ? *(const float2*)&se[grow * HID + k]
                         : *(const float2*)&raw[grow * HID + k - HID];
    }
    if (k < HID)     return *(const float2*)&se[grow * HID + k];
    if (k < 2 * HID) return *(const float2*)&g_sm[grow * HID + k - HID];
    {
        float2 a = *(const float2*)&se[grow * HID + k - 2 * HID];
        float2 b = *(const float2*)&g_sm[grow * HID + k - 2 * HID];
        return make_float2(a.x * b.x, a.y * b.y);
    }
}

template <int STAGE>
__device__ __forceinline__ void gemm_body(const float* __restrict__ se,
                                          const float* __restrict__ mem,
                                          const float* __restrict__ raw,
                                          const float* __restrict__ bias,
                                          float* __restrict__ dout,
                                          int rows)
{
    constexpr int NC = (STAGE == 0) ? 2 : (STAGE == 1 ? 4 : 5);
    constexpr int CBASE = (STAGE == 0) ? 0 : (STAGE == 1 ? 2 : 6);
    extern __shared__ __align__(16) char smc[];
    float* bias_s = (float*)(smc + OFF_BIAS);
    const uint smb = (uint)__cvta_generic_to_shared(smc);
    const int tid = threadIdx.x;
    const int wid = tid >> 5;
    const int lane = tid & 31;
    const int mw = wid & 3;          // m quadrant (32 rows)
    const int ng = wid >> 2;         // n half: 0 -> nt 0..6, 1 -> nt 7..12
    const int NT = 7 - ng;           // 7 or 6 tiles
    const int row0 = blockIdx.x * MT;

    if (tid < 104) bias_s[tid] = (tid < HID) ? bias[tid] : 0.0f;

    float acc[2][7][4];
#pragma unroll
    for (int mt = 0; mt < 2; mt++)
#pragma unroll
        for (int j = 0; j < 7; j++)
#pragma unroll
            for (int z = 0; z < 4; z++) acc[mt][j][z] = 0.0f;

    const uint boff2 = (uint)(((lane & 7) * ASTB + ((lane >> 3) & 1) * 8) * 2);
    const uint nrow4 = (uint)((lane & 7) | ((lane >> 1) & 8));
    const uint boff4 = (uint)((nrow4 * ASTB + ((lane >> 3) & 1) * 8) * 2);
    const char* bsrc = (const char*)&g_Bimg[CBASE][0][0];

#pragma unroll
    for (int it = 0; it < 8; it++) {
        int idx = tid + it * 256;
        if (idx < BCHK / 16) cpa16(smb + (uint)(idx * 16), bsrc + idx * 16);
    }
    asm volatile("cp.async.commit_group;");

    const int r0 = row0 + mw * 32 + (lane >> 2);    // tile0 low row
    int buf = 0;

    for (int c = 0; c < NC; c++) {
        if (c + 1 < NC) {
            const char* src = bsrc + (c + 1) * BCHK;
            const uint dst = smb + (uint)((buf ^ 1) * BCHK);
#pragma unroll
            for (int it = 0; it < 8; it++) {
                int idx = tid + it * 256;
                if (idx < BCHK / 16) cpa16(dst + (uint)(idx * 16), src + idx * 16);
            }
            asm volatile("cp.async.commit_group;");
            asm volatile("cp.async.wait_group 1;" ::: "memory");
        } else {
            asm volatile("cp.async.wait_group 0;" ::: "memory");
        }
        __syncthreads();

        const uint bB = smb + (uint)(buf * BCHK);

#pragma unroll
        for (int ks = 0; ks < 4; ks++) {
            const int kb = c * KCH + ks * 16 + (lane & 3) * 2;
            uint ah[2][4], al[2][4];
#pragma unroll
            for (int mt = 0; mt < 2; mt++) {
                const int rr = r0 + mt * 16;
                float2 x0 = ldx<STAGE>(se, mem, raw, rr,     kb,     rows);
                float2 x1 = ldx<STAGE>(se, mem, raw, rr + 8, kb,     rows);
                float2 x2 = ldx<STAGE>(se, mem, raw, rr,     kb + 8, rows);
                float2 x3 = ldx<STAGE>(se, mem, raw, rr + 8, kb + 8, rows);
                sp2(x0, ah[mt][0], al[mt][0]);
                sp2(x1, ah[mt][1], al[mt][1]);
                sp2(x2, ah[mt][2], al[mt][2]);
                sp2(x3, ah[mt][3], al[mt][3]);
            }
            const uint kby = (uint)(ks * 32);
#pragma unroll
            for (int np = 0; np < 3; np++) {
                const uint nb = (uint)((ng * 56 + np * 16) * ASTB * 2) + kby;
                uint bh0, bh1, bh2, bh3, bl0, bl1, bl2, bl3;
                LDSM4(bh0, bh1, bh2, bh3, bB + boff4 + nb);
                LDSM4(bl0, bl1, bl2, bl3, bB + BSPL + boff4 + nb);
#pragma unroll
                for (int mt = 0; mt < 2; mt++) {
                    mma16816(acc[mt][2 * np],     ah[mt], bh0, bh1);
                    mma16816(acc[mt][2 * np],     ah[mt], bl0, bl1);
                    mma16816(acc[mt][2 * np],     al[mt], bh0, bh1);
                    mma16816(acc[mt][2 * np + 1], ah[mt], bh2, bh3);
                    mma16816(acc[mt][2 * np + 1], ah[mt], bl2, bl3);
                    mma16816(acc[mt][2 * np + 1], al[mt], bh2, bh3);
                }
            }
            if (ng == 0) {   // nt 6 (cols 48..55)
                const uint nb = (uint)(48 * ASTB * 2) + kby;
                uint bh0, bh1, bl0, bl1;
                LDSM2(bh0, bh1, bB + boff2 + nb);
                LDSM2(bl0, bl1, bB + BSPL + boff2 + nb);
#pragma unroll
                for (int mt = 0; mt < 2; mt++) {
                    mma16816(acc[mt][6], ah[mt], bh0, bh1);
                    mma16816(acc[mt][6], ah[mt], bl0, bl1);
                    mma16816(acc[mt][6], al[mt], bh0, bh1);
                }
            }
        }
        __syncthreads();
        buf ^= 1;
    }

    // ---- epilogue ----
    const int g = lane >> 2, tg = lane & 3;
#pragma unroll
    for (int mt = 0; mt < 2; mt++) {
#pragma unroll
        for (int j = 0; j < 7; j++) {
            if (j >= NT) break;
            const int nt = ng * 7 + j;
            const int n0 = nt * 8 + tg * 2;
            if (n0 >= HID) continue;
            const float bz0 = bias_s[n0], bz1 = bias_s[n0 + 1];
#pragma unroll
            for (int half = 0; half < 2; half++) {
                const int rr = row0 + mw * 32 + mt * 16 + g + half * 8;
                if (rr >= rows) continue;
                float z0 = acc[mt][j][half * 2]     + bz0;
                float z1 = acc[mt][j][half * 2 + 1] + bz1;
                const int off = rr * HID + n0;
                float2 o;
                if (STAGE < 2) {
                    o.x = tanhf(z0); o.y = tanhf(z1);
                    float* dst = (STAGE == 0) ? g_m4 : g_s4;
                    *(float2*)&dst[off] = o;
                } else {
                    float2 sev = *(const float2*)&se[off];
                    float2 smv = *(const float2*)&g_sm[off];
                    o.x = fmaf(sigf(z0), smv.x - sev.x, sev.x);
                    o.y = fmaf(sigf(z1), smv.y - sev.y, sev.y);
                    *(float2*)&dout[off] = o;
                }
            }
        }
    }
}

__global__ __launch_bounds__(256, 2)
void gemm01(const float* __restrict__ se, const float* __restrict__ mem,
            const float* __restrict__ raw,
            const float* __restrict__ b_mem, const float* __restrict__ b_sub,
            int rows)
{
    if (blockIdx.y == 0) gemm_body<0>(se, mem, raw, b_mem, nullptr, rows);
    else                 gemm_body<1>(se, mem, raw, b_sub, nullptr, rows);
}

__global__ __launch_bounds__(256, 2)
void gemm2(const float* __restrict__ se, const float* __restrict__ mem,
           const float* __restrict__ raw, const float* __restrict__ b_gate,
           float* __restrict__ dout, int rows)
{
    gemm_body<2>(se, mem, raw, b_gate, dout, rows);
}

// ---------------------------------------------------------------------------
// Attention: one warp per batch, 8 per CTA; LDS.128 score loop.
// ---------------------------------------------------------------------------
__global__ __launch_bounds__(256)
void attn_kernel(const float* __restrict__ memory,
                 const int* __restrict__ sub_len,
                 int B)
{
    __shared__ __align__(16) float s4s[8][500];
    __shared__ __align__(16) float m4s[8][500];
    __shared__ float atts[8][25];
    __shared__ __align__(16) ull attd[8][25];

    const int w = threadIdx.x >> 5;
    const int lane = threadIdx.x & 31;
    const int b = blockIdx.x * 8 + w;
    if (b >= B) return;

    for (int i = lane; i < 125; i += 32) {
        *(float4*)&s4s[w][4 * i] = *(const float4*)&g_s4[b * 500 + 4 * i];
        *(float4*)&m4s[w][4 * i] = *(const float4*)&g_m4[b * 500 + 4 * i];
    }
    __syncwarp();

    if (lane < 25) {
        const int q = lane / 5, kk = lane % 5;
        float a = 0.0f;
#pragma unroll
        for (int j = 0; j < 25; j++) {
            float4 sv = *(const float4*)&s4s[w][q * 100 + 4 * j];
            float4 mv = *(const float4*)&m4s[w][kk * 100 + 4 * j];
            a += sv.x * mv.x + sv.y * mv.y + sv.z * mv.z + sv.w * mv.w;
        }
        atts[w][lane] = a;
    }
    __syncwarp();

    if (lane < 5) {
        const int q = lane;
        const int len = sub_len[b];
        float a[5];
#pragma unroll
        for (int i = 0; i < 5; i++) a[i] = atts[w][q * 5 + i];
        float m = a[0];
#pragma unroll
        for (int i = 1; i < 5; i++) m = fmaxf(m, a[i]);
        float e[5], s = 0.0f;
#pragma unroll
        for (int i = 0; i < 5; i++) { e[i] = __expf(a[i] - m); s += e[i]; }
        const float inv = (q < len) ? (1.0f / s) : 0.0f;
#pragma unroll
        for (int i = 0; i < 5; i++) {
            float r = e[i] * inv;
            attd[w][q * 5 + i] = pack2(r, r);
        }
    }
    __syncwarp();

    if (lane < 25) {
        const int c0 = 4 * lane;
        ull acc[5][2];
#pragma unroll
        for (int q = 0; q < 5; q++) { acc[q][0] = 0ull; acc[q][1] = 0ull; }
#pragma unroll
        for (int kk = 0; kk < 5; kk++) {
            ulonglong2 mv = *(const ulonglong2*)&memory[b * 500 + kk * 100 + c0];
#pragma unroll
            for (int q = 0; q < 5; q++) {
                ull ad = attd[w][q * 5 + kk];
                acc[q][0] = fma2(ad, mv.x, acc[q][0]);
                acc[q][1] = fma2(ad, mv.y, acc[q][1]);
            }
        }
#pragma unroll
        for (int q = 0; q < 5; q++) {
            float2 a01 = unpack2(acc[q][0]);
            float2 a23 = unpack2(acc[q][1]);
            float4 o; o.x = a01.x; o.y = a01.y; o.z = a23.x; o.w = a23.y;
            *(float4*)&g_sm[b * 500 + q * 100 + c0] = o;
        }
    }
}

// ---------------------------------------------------------------------------
extern "C" void kernel_launch(void* const* d_in, const int* in_sizes, int n_in,
                              void* d_out, int out_size)
{
    const float* sub_emb = (const float*)d_in[0];
    const float* memory  = (const float*)d_in[1];
    const int*   sub_len = (const int*)d_in[2];
    const float* raw     = (const float*)d_in[3];
    const float* W_mem   = (const float*)d_in[4];
    const float* b_mem   = (const float*)d_in[5];
    const float* W_sub   = (const float*)d_in[6];
    const float* b_sub   = (const float*)d_in[7];
    const float* W_gate  = (const float*)d_in[8];
    const float* b_gate  = (const float*)d_in[9];
    float* out = (float*)d_out;
    const int B = in_sizes[2];
    const int rows = B * 5;
    const int tiles = (rows + MT - 1) / MT;

    cudaFuncSetAttribute(gemm01, cudaFuncAttributeMaxDynamicSharedMemorySize, GSMEM);
    cudaFuncSetAttribute(gemm2,  cudaFuncAttributeMaxDynamicSharedMemorySize, GSMEM);

    prep_kernel<<<(11 * 104 * KCH + 255) / 256, 256>>>(W_mem, W_sub, W_gate);
    gemm01<<<dim3(tiles, 2), 256, GSMEM>>>(sub_emb, memory, raw, b_mem, b_sub, rows);
    attn_kernel<<<(B + 7) / 8, 256>>>(memory, sub_len, B);
    gemm2<<<tiles, 256, GSMEM>>>(sub_emb, memory, raw, b_gate, out, rows);
}

// round 12
// speedup vs baseline: 1.5761x; 1.5761x over previous
#include <cuda_runtime.h>
#include <cuda_bf16.h>
#include <cstdint>

// ---------------------------------------------------------------------------
// Reading_memory R12: R8 layout (1 m-tile/warp, x4 B LDSM, cp.async dbl-buf B)
// + chunk-level A prefetch into registers (hide A LDG latency under MMAs).
// ---------------------------------------------------------------------------

#define B_MAX 65536
#define HID 100
#define MT   128
#define KCH  64
#define ASTB 72                    // B image k-stride (elems)
#define BSPL (104 * ASTB * 2)      // bytes per split
#define BCHK (2 * BSPL)
typedef unsigned long long ull;
typedef unsigned int uint;

__device__ __align__(16) static float g_m4[B_MAX * 500];
__device__ __align__(16) static float g_s4[B_MAX * 500];
__device__ __align__(16) static float g_sm[B_MAX * 500];
__device__ __align__(16) static __nv_bfloat16 g_Bimg[11][2][104 * ASTB];

__device__ __forceinline__ float sigf(float x) { return 1.0f / (1.0f + __expf(-x)); }

__device__ __forceinline__ ull fma2(ull a, ull b, ull c) {
    ull d;
    asm("fma.rn.f32x2 %0, %1, %2, %3;" : "=l"(d) : "l"(a), "l"(b), "l"(c));
    return d;
}
__device__ __forceinline__ ull pack2(float lo, float hi) {
    ull r;
    asm("mov.b64 %0, {%1, %2};" : "=l"(r) : "r"(__float_as_uint(lo)), "r"(__float_as_uint(hi)));
    return r;
}
__device__ __forceinline__ float2 unpack2(ull v) {
    uint lo, hi;
    asm("mov.b64 {%0, %1}, %2;" : "=r"(lo), "=r"(hi) : "l"(v));
    float2 r; r.x = __uint_as_float(lo); r.y = __uint_as_float(hi);
    return r;
}
__device__ __forceinline__ void sp2(float2 v, uint& h, uint& l) {
    uint hh;
    asm("cvt.rn.bf16x2.f32 %0, %1, %2;" : "=r"(hh) : "f"(v.y), "f"(v.x));
    float rx = v.x - __uint_as_float(hh << 16);
    float ry = v.y - __uint_as_float(hh & 0xFFFF0000u);
    asm("cvt.rn.bf16x2.f32 %0, %1, %2;" : "=r"(l) : "f"(ry), "f"(rx));
    h = hh;
}

#define LDSM2(d0, d1, addr) \
    asm volatile("ldmatrix.sync.aligned.m8n8.x2.shared.b16 {%0,%1}, [%2];" \
                 : "=r"(d0), "=r"(d1) : "r"(addr))
#define LDSM4(d0, d1, d2, d3, addr) \
    asm volatile("ldmatrix.sync.aligned.m8n8.x4.shared.b16 {%0,%1,%2,%3}, [%4];" \
                 : "=r"(d0), "=r"(d1), "=r"(d2), "=r"(d3) : "r"(addr))

__device__ __forceinline__ void mma16816(float c[4], uint a0, uint a1, uint a2, uint a3,
                                         uint b0, uint b1) {
    asm volatile(
        "mma.sync.aligned.m16n8k16.row.col.f32.bf16.bf16.f32 "
        "{%0,%1,%2,%3}, {%4,%5,%6,%7}, {%8,%9}, {%0,%1,%2,%3};"
        : "+f"(c[0]), "+f"(c[1]), "+f"(c[2]), "+f"(c[3])
        : "r"(a0), "r"(a1), "r"(a2), "r"(a3), "r"(b0), "r"(b1));
}

__device__ __forceinline__ void cpa16(uint saddr, const void* src) {
    asm volatile("cp.async.cg.shared.global [%0], [%1], 16;" :: "r"(saddr), "l"(src));
}

// ---------------------------------------------------------------------------
__global__ void prep_kernel(const float* __restrict__ Wm,
                            const float* __restrict__ Ws,
                            const float* __restrict__ Wg)
{
    const int idx = blockIdx.x * blockDim.x + threadIdx.x;
    const int PER = 104 * KCH;
    if (idx >= 11 * PER) return;
    const int cidx = idx / PER;
    const int rem = idx - cidx * PER;
    const int n = rem / KCH, k = rem - n * KCH;
    int c, KS;
    const float* W;
    if (cidx < 2)      { W = Wm; c = cidx;     KS = 100; }
    else if (cidx < 6) { W = Ws; c = cidx - 2; KS = 200; }
    else               { W = Wg; c = cidx - 6; KS = 300; }
    const int gk = c * KCH + k;
    float v = (n < HID && gk < KS) ? W[gk * HID + n] : 0.0f;
    __nv_bfloat16 hi = __float2bfloat16(v);
    __nv_bfloat16 lo = __float2bfloat16(v - __bfloat162float(hi));
    g_Bimg[cidx][0][n * ASTB + k] = hi;
    g_Bimg[cidx][1][n * ASTB + k] = lo;
}

// ---------------------------------------------------------------------------
#define OFF_BIAS (2 * BCHK)
#define GSMEM (OFF_BIAS + 104 * 4)

template <int STAGE>
__device__ __forceinline__ float2 ldx(const float* __restrict__ se,
                                      const float* __restrict__ mem,
                                      const float* __restrict__ raw,
                                      int grow, int k, int rows)
{
    constexpr int KS = (STAGE == 0) ? 100 : (STAGE == 1 ? 200 : 300);
    float2 z = make_float2(0.f, 0.f);
    if (grow >= rows || k >= KS) return z;
    if (STAGE == 0) return *(const float2*)&mem[grow * HID + k];
    if (STAGE == 1) {
        return (k < HID) ? *(const float2*)&se[grow * HID + k]
                         : *(const float2*)&raw[grow * HID + k - HID];
    }
    if (k < HID)     return *(const float2*)&se[grow * HID + k];
    if (k < 2 * HID) return *(const float2*)&g_sm[grow * HID + k - HID];
    {
        float2 a = *(const float2*)&se[grow * HID + k - 2 * HID];
        float2 b = *(const float2*)&g_sm[grow * HID + k - 2 * HID];
        return make_float2(a.x * b.x, a.y * b.y);
    }
}

// load all A raw operands for one chunk: [ks][frag] frag order (lo,kb),(hi,kb),(lo,kb+8),(hi,kb+8)
template <int STAGE>
__device__ __forceinline__ void loadA(float2 x[4][4],
                                      const float* __restrict__ se,
                                      const float* __restrict__ mem,
                                      const float* __restrict__ raw,
                                      int r_lo, int r_hi, int c, int lane, int rows)
{
#pragma unroll
    for (int ks = 0; ks < 4; ks++) {
        const int kb = c * KCH + ks * 16 + (lane & 3) * 2;
        x[ks][0] = ldx<STAGE>(se, mem, raw, r_lo, kb,     rows);
        x[ks][1] = ldx<STAGE>(se, mem, raw, r_hi, kb,     rows);
        x[ks][2] = ldx<STAGE>(se, mem, raw, r_lo, kb + 8, rows);
        x[ks][3] = ldx<STAGE>(se, mem, raw, r_hi, kb + 8, rows);
    }
}

template <int STAGE>
__device__ __forceinline__ void gemm_body(const float* __restrict__ se,
                                          const float* __restrict__ mem,
                                          const float* __restrict__ raw,
                                          const float* __restrict__ bias,
                                          float* __restrict__ dout,
                                          int rows)
{
    constexpr int NC = (STAGE == 0) ? 2 : (STAGE == 1 ? 4 : 5);
    constexpr int CBASE = (STAGE == 0) ? 0 : (STAGE == 1 ? 2 : 6);
    extern __shared__ __align__(16) char smc[];
    float* bias_s = (float*)(smc + OFF_BIAS);
    const uint smb = (uint)__cvta_generic_to_shared(smc);
    const int tid = threadIdx.x;
    const int wid = tid >> 5;
    const int lane = tid & 31;
    const int row0 = blockIdx.x * MT;

    if (tid < 104) bias_s[tid] = (tid < HID) ? bias[tid] : 0.0f;

    float acc[13][4];
#pragma unroll
    for (int nt = 0; nt < 13; nt++)
#pragma unroll
        for (int j = 0; j < 4; j++) acc[nt][j] = 0.0f;

    const uint boff2 = (uint)(((lane & 7) * ASTB + ((lane >> 3) & 1) * 8) * 2);
    const uint nrow4 = (uint)((lane & 7) | ((lane >> 1) & 8));
    const uint boff4 = (uint)((nrow4 * ASTB + ((lane >> 3) & 1) * 8) * 2);
    const char* bsrc = (const char*)&g_Bimg[CBASE][0][0];

#pragma unroll
    for (int it = 0; it < 8; it++) {
        int idx = tid + it * 256;
        if (idx < BCHK / 16) cpa16(smb + (uint)(idx * 16), bsrc + idx * 16);
    }
    asm volatile("cp.async.commit_group;");

    const int r_lo = row0 + wid * 16 + (lane >> 2);
    const int r_hi = r_lo + 8;
    int buf = 0;

    float2 xa[4][4];
    loadA<STAGE>(xa, se, mem, raw, r_lo, r_hi, 0, lane, rows);

#pragma unroll
    for (int c = 0; c < NC; c++) {
        if (c + 1 < NC) {
            const char* src = bsrc + (c + 1) * BCHK;
            const uint dst = smb + (uint)((buf ^ 1) * BCHK);
#pragma unroll
            for (int it = 0; it < 8; it++) {
                int idx = tid + it * 256;
                if (idx < BCHK / 16) cpa16(dst + (uint)(idx * 16), src + idx * 16);
            }
            asm volatile("cp.async.commit_group;");
            asm volatile("cp.async.wait_group 1;" ::: "memory");
        } else {
            asm volatile("cp.async.wait_group 0;" ::: "memory");
        }
        __syncthreads();

        // prefetch next chunk's A while the MMA phase runs
        float2 xn[4][4];
        if (c + 1 < NC)
            loadA<STAGE>(xn, se, mem, raw, r_lo, r_hi, c + 1, lane, rows);

        const uint bB = smb + (uint)(buf * BCHK);

#pragma unroll
        for (int ks = 0; ks < 4; ks++) {
            uint ah0, ah1, ah2, ah3, al0, al1, al2, al3;
            sp2(xa[ks][0], ah0, al0);
            sp2(xa[ks][1], ah1, al1);
            sp2(xa[ks][2], ah2, al2);
            sp2(xa[ks][3], ah3, al3);
            const uint kby = (uint)(ks * 32);
#pragma unroll
            for (int np = 0; np < 6; np++) {
                const uint nb = (uint)(np * 16 * ASTB * 2) + kby;
                uint bh0, bh1, bh2, bh3, bl0, bl1, bl2, bl3;
                LDSM4(bh0, bh1, bh2, bh3, bB + boff4 + nb);
                LDSM4(bl0, bl1, bl2, bl3, bB + BSPL + boff4 + nb);
                mma16816(acc[2 * np],     ah0, ah1, ah2, ah3, bh0, bh1);
                mma16816(acc[2 * np],     ah0, ah1, ah2, ah3, bl0, bl1);
                mma16816(acc[2 * np],     al0, al1, al2, al3, bh0, bh1);
                mma16816(acc[2 * np + 1], ah0, ah1, ah2, ah3, bh2, bh3);
                mma16816(acc[2 * np + 1], ah0, ah1, ah2, ah3, bl2, bl3);
                mma16816(acc[2 * np + 1], al0, al1, al2, al3, bh2, bh3);
            }
            {   // last n-tile (nt=12, cols 96..103)
                const uint nb = (uint)(12 * 8 * ASTB * 2) + kby;
                uint bh0, bh1, bl0, bl1;
                LDSM2(bh0, bh1, bB + boff2 + nb);
                LDSM2(bl0, bl1, bB + BSPL + boff2 + nb);
                mma16816(acc[12], ah0, ah1, ah2, ah3, bh0, bh1);
                mma16816(acc[12], ah0, ah1, ah2, ah3, bl0, bl1);
                mma16816(acc[12], al0, al1, al2, al3, bh0, bh1);
            }
        }

        if (c + 1 < NC) {
#pragma unroll
            for (int ks = 0; ks < 4; ks++)
#pragma unroll
                for (int j = 0; j < 4; j++) xa[ks][j] = xn[ks][j];
        }
        __syncthreads();
        buf ^= 1;
    }

    // ---- epilogue ----
    const int g = lane >> 2, tg = lane & 3;
    const int r0 = row0 + wid * 16 + g;
    const int r1 = r0 + 8;
#pragma unroll
    for (int nt = 0; nt < 13; nt++) {
        const int n0 = nt * 8 + tg * 2;
        if (n0 >= HID) continue;
        const float bz0 = bias_s[n0], bz1 = bias_s[n0 + 1];
#pragma unroll
        for (int half = 0; half < 2; half++) {
            const int rr = half ? r1 : r0;
            if (rr >= rows) continue;
            float z0 = acc[nt][half * 2]     + bz0;
            float z1 = acc[nt][half * 2 + 1] + bz1;
            const int off = rr * HID + n0;
            float2 o;
            if (STAGE < 2) {
                o.x = tanhf(z0); o.y = tanhf(z1);
                float* dst = (STAGE == 0) ? g_m4 : g_s4;
                *(float2*)&dst[off] = o;
            } else {
                float2 sev = *(const float2*)&se[off];
                float2 smv = *(const float2*)&g_sm[off];
                o.x = fmaf(sigf(z0), smv.x - sev.x, sev.x);
                o.y = fmaf(sigf(z1), smv.y - sev.y, sev.y);
                *(float2*)&dout[off] = o;
            }
        }
    }
}

__global__ __launch_bounds__(256, 2)
void gemm01(const float* __restrict__ se, const float* __restrict__ mem,
            const float* __restrict__ raw,
            const float* __restrict__ b_mem, const float* __restrict__ b_sub,
            int rows)
{
    if (blockIdx.y == 0) gemm_body<0>(se, mem, raw, b_mem, nullptr, rows);
    else                 gemm_body<1>(se, mem, raw, b_sub, nullptr, rows);
}

__global__ __launch_bounds__(256, 2)
void gemm2(const float* __restrict__ se, const float* __restrict__ mem,
           const float* __restrict__ raw, const float* __restrict__ b_gate,
           float* __restrict__ dout, int rows)
{
    gemm_body<2>(se, mem, raw, b_gate, dout, rows);
}

// ---------------------------------------------------------------------------
// Attention: one warp per batch, 8 per CTA; LDS.128 score loop.
// ---------------------------------------------------------------------------
__global__ __launch_bounds__(256)
void attn_kernel(const float* __restrict__ memory,
                 const int* __restrict__ sub_len,
                 int B)
{
    __shared__ __align__(16) float s4s[8][500];
    __shared__ __align__(16) float m4s[8][500];
    __shared__ float atts[8][25];
    __shared__ __align__(16) ull attd[8][25];

    const int w = threadIdx.x >> 5;
    const int lane = threadIdx.x & 31;
    const int b = blockIdx.x * 8 + w;
    if (b >= B) return;

    for (int i = lane; i < 125; i += 32) {
        *(float4*)&s4s[w][4 * i] = *(const float4*)&g_s4[b * 500 + 4 * i];
        *(float4*)&m4s[w][4 * i] = *(const float4*)&g_m4[b * 500 + 4 * i];
    }
    __syncwarp();

    if (lane < 25) {
        const int q = lane / 5, kk = lane % 5;
        float a = 0.0f;
#pragma unroll
        for (int j = 0; j < 25; j++) {
            float4 sv = *(const float4*)&s4s[w][q * 100 + 4 * j];
            float4 mv = *(const float4*)&m4s[w][kk * 100 + 4 * j];
            a += sv.x * mv.x + sv.y * mv.y + sv.z * mv.z + sv.w * mv.w;
        }
        atts[w][lane] = a;
    }
    __syncwarp();

    if (lane < 5) {
        const int q = lane;
        const int len = sub_len[b];
        float a[5];
#pragma unroll
        for (int i = 0; i < 5; i++) a[i] = atts[w][q * 5 + i];
        float m = a[0];
#pragma unroll
        for (int i = 1; i < 5; i++) m = fmaxf(m, a[i]);
        float e[5], s = 0.0f;
#pragma unroll
        for (int i = 0; i < 5; i++) { e[i] = __expf(a[i] - m); s += e[i]; }
        const float inv = (q < len) ? (1.0f / s) : 0.0f;
#pragma unroll
        for (int i = 0; i < 5; i++) {
            float r = e[i] * inv;
            attd[w][q * 5 + i] = pack2(r, r);
        }
    }
    __syncwarp();

    if (lane < 25) {
        const int c0 = 4 * lane;
        ull acc[5][2];
#pragma unroll
        for (int q = 0; q < 5; q++) { acc[q][0] = 0ull; acc[q][1] = 0ull; }
#pragma unroll
        for (int kk = 0; kk < 5; kk++) {
            ulonglong2 mv = *(const ulonglong2*)&memory[b * 500 + kk * 100 + c0];
#pragma unroll
            for (int q = 0; q < 5; q++) {
                ull ad = attd[w][q * 5 + kk];
                acc[q][0] = fma2(ad, mv.x, acc[q][0]);
                acc[q][1] = fma2(ad, mv.y, acc[q][1]);
            }
        }
#pragma unroll
        for (int q = 0; q < 5; q++) {
            float2 a01 = unpack2(acc[q][0]);
            float2 a23 = unpack2(acc[q][1]);
            float4 o; o.x = a01.x; o.y = a01.y; o.z = a23.x; o.w = a23.y;
            *(float4*)&g_sm[b * 500 + q * 100 + c0] = o;
        }
    }
}

// ---------------------------------------------------------------------------
extern "C" void kernel_launch(void* const* d_in, const int* in_sizes, int n_in,
                              void* d_out, int out_size)
{
    const float* sub_emb = (const float*)d_in[0];
    const float* memory  = (const float*)d_in[1];
    const int*   sub_len = (const int*)d_in[2];
    const float* raw     = (const float*)d_in[3];
    const float* W_mem   = (const float*)d_in[4];
    const float* b_mem   = (const float*)d_in[5];
    const float* W_sub   = (const float*)d_in[6];
    const float* b_sub   = (const float*)d_in[7];
    const float* W_gate  = (const float*)d_in[8];
    const float* b_gate  = (const float*)d_in[9];
    float* out = (float*)d_out;
    const int B = in_sizes[2];
    const int rows = B * 5;
    const int tiles = (rows + MT - 1) / MT;

    cudaFuncSetAttribute(gemm01, cudaFuncAttributeMaxDynamicSharedMemorySize, GSMEM);
    cudaFuncSetAttribute(gemm2,  cudaFuncAttributeMaxDynamicSharedMemorySize, GSMEM);

    prep_kernel<<<(11 * 104 * KCH + 255) / 256, 256>>>(W_mem, W_sub, W_gate);
    gemm01<<<dim3(tiles, 2), 256, GSMEM>>>(sub_emb, memory, raw, b_mem, b_sub, rows);
    attn_kernel<<<(B + 7) / 8, 256>>>(memory, sub_len, B);
    gemm2<<<tiles, 256, GSMEM>>>(sub_emb, memory, raw, b_gate, out, rows);
}

// round 14
// speedup vs baseline: 1.6090x; 1.0209x over previous
#include <cuda_runtime.h>
#include <cuda_bf16.h>
#include <cstdint>

// ---------------------------------------------------------------------------
// Reading_memory R13: R12 + MMA dependency-distance widening.
// n-tile pairs per group: 12 MMAs round-robin over 4 independent accumulators
// (tail group: 5). A prefetch at 2-ks granularity to stay <=128 regs.
// ---------------------------------------------------------------------------

#define B_MAX 65536
#define HID 100
#define MT   128
#define KCH  64
#define ASTB 72                    // B image k-stride (elems)
#define BSPL (104 * ASTB * 2)      // bytes per split
#define BCHK (2 * BSPL)
typedef unsigned long long ull;
typedef unsigned int uint;

__device__ __align__(16) static float g_m4[B_MAX * 500];
__device__ __align__(16) static float g_s4[B_MAX * 500];
__device__ __align__(16) static float g_sm[B_MAX * 500];
__device__ __align__(16) static __nv_bfloat16 g_Bimg[11][2][104 * ASTB];

__device__ __forceinline__ float sigf(float x) { return 1.0f / (1.0f + __expf(-x)); }

__device__ __forceinline__ ull fma2(ull a, ull b, ull c) {
    ull d;
    asm("fma.rn.f32x2 %0, %1, %2, %3;" : "=l"(d) : "l"(a), "l"(b), "l"(c));
    return d;
}
__device__ __forceinline__ ull pack2(float lo, float hi) {
    ull r;
    asm("mov.b64 %0, {%1, %2};" : "=l"(r) : "r"(__float_as_uint(lo)), "r"(__float_as_uint(hi)));
    return r;
}
__device__ __forceinline__ float2 unpack2(ull v) {
    uint lo, hi;
    asm("mov.b64 {%0, %1}, %2;" : "=r"(lo), "=r"(hi) : "l"(v));
    float2 r; r.x = __uint_as_float(lo); r.y = __uint_as_float(hi);
    return r;
}
__device__ __forceinline__ void sp2(float2 v, uint& h, uint& l) {
    uint hh;
    asm("cvt.rn.bf16x2.f32 %0, %1, %2;" : "=r"(hh) : "f"(v.y), "f"(v.x));
    float rx = v.x - __uint_as_float(hh << 16);
    float ry = v.y - __uint_as_float(hh & 0xFFFF0000u);
    asm("cvt.rn.bf16x2.f32 %0, %1, %2;" : "=r"(l) : "f"(ry), "f"(rx));
    h = hh;
}

#define LDSM2(d0, d1, addr) \
    asm volatile("ldmatrix.sync.aligned.m8n8.x2.shared.b16 {%0,%1}, [%2];" \
                 : "=r"(d0), "=r"(d1) : "r"(addr))
#define LDSM4(d0, d1, d2, d3, addr) \
    asm volatile("ldmatrix.sync.aligned.m8n8.x4.shared.b16 {%0,%1,%2,%3}, [%4];" \
                 : "=r"(d0), "=r"(d1), "=r"(d2), "=r"(d3) : "r"(addr))

__device__ __forceinline__ void mma16816(float c[4], uint a0, uint a1, uint a2, uint a3,
                                         uint b0, uint b1) {
    asm volatile(
        "mma.sync.aligned.m16n8k16.row.col.f32.bf16.bf16.f32 "
        "{%0,%1,%2,%3}, {%4,%5,%6,%7}, {%8,%9}, {%0,%1,%2,%3};"
        : "+f"(c[0]), "+f"(c[1]), "+f"(c[2]), "+f"(c[3])
        : "r"(a0), "r"(a1), "r"(a2), "r"(a3), "r"(b0), "r"(b1));
}

__device__ __forceinline__ void cpa16(uint saddr, const void* src) {
    asm volatile("cp.async.cg.shared.global [%0], [%1], 16;" :: "r"(saddr), "l"(src));
}

// ---------------------------------------------------------------------------
__global__ void prep_kernel(const float* __restrict__ Wm,
                            const float* __restrict__ Ws,
                            const float* __restrict__ Wg)
{
    const int idx = blockIdx.x * blockDim.x + threadIdx.x;
    const int PER = 104 * KCH;
    if (idx >= 11 * PER) return;
    const int cidx = idx / PER;
    const int rem = idx - cidx * PER;
    const int n = rem / KCH, k = rem - n * KCH;
    int c, KS;
    const float* W;
    if (cidx < 2)      { W = Wm; c = cidx;     KS = 100; }
    else if (cidx < 6) { W = Ws; c = cidx - 2; KS = 200; }
    else               { W = Wg; c = cidx - 6; KS = 300; }
    const int gk = c * KCH + k;
    float v = (n < HID && gk < KS) ? W[gk * HID + n] : 0.0f;
    __nv_bfloat16 hi = __float2bfloat16(v);
    __nv_bfloat16 lo = __float2bfloat16(v - __bfloat162float(hi));
    g_Bimg[cidx][0][n * ASTB + k] = hi;
    g_Bimg[cidx][1][n * ASTB + k] = lo;
}

// ---------------------------------------------------------------------------
#define OFF_BIAS (2 * BCHK)
#define GSMEM (OFF_BIAS + 104 * 4)

template <int STAGE>
__device__ __forceinline__ float2 ldx(const float* __restrict__ se,
                                      const float* __restrict__ mem,
                                      const float* __restrict__ raw,
                                      int grow, int k, int rows)
{
    constexpr int KS = (STAGE == 0) ? 100 : (STAGE == 1 ? 200 : 300);
    float2 z = make_float2(0.f, 0.f);
    if (grow >= rows || k >= KS) return z;
    if (STAGE == 0) return *(const float2*)&mem[grow * HID + k];
    if (STAGE == 1) {
        return (k < HID) ? *(const float2*)&se[grow * HID + k]
                         : *(const float2*)&raw[grow * HID + k - HID];
    }
    if (k < HID)     return *(const float2*)&se[grow * HID + k];
    if (k < 2 * HID) return *(const float2*)&g_sm[grow * HID + k - HID];
    {
        float2 a = *(const float2*)&se[grow * HID + k - 2 * HID];
        float2 b = *(const float2*)&g_sm[grow * HID + k - 2 * HID];
        return make_float2(a.x * b.x, a.y * b.y);
    }
}

// load A raw operands for a 2-ks half-chunk (half = 0 or 1)
template <int STAGE>
__device__ __forceinline__ void loadA2(float2 x[2][4],
                                       const float* __restrict__ se,
                                       const float* __restrict__ mem,
                                       const float* __restrict__ raw,
                                       int r_lo, int r_hi, int c, int half,
                                       int lane, int rows)
{
#pragma unroll
    for (int ks2 = 0; ks2 < 2; ks2++) {
        const int kb = c * KCH + (half * 2 + ks2) * 16 + (lane & 3) * 2;
        x[ks2][0] = ldx<STAGE>(se, mem, raw, r_lo, kb,     rows);
        x[ks2][1] = ldx<STAGE>(se, mem, raw, r_hi, kb,     rows);
        x[ks2][2] = ldx<STAGE>(se, mem, raw, r_lo, kb + 8, rows);
        x[ks2][3] = ldx<STAGE>(se, mem, raw, r_hi, kb + 8, rows);
    }
}

// process a 2-ks group: dep-distance-4/5 interleaved MMA streams
__device__ __forceinline__ void mma_group(float acc[13][4], const float2 x[2][4],
                                          uint bB, uint boff4, uint boff2, int ksbase)
{
#pragma unroll
    for (int ks2 = 0; ks2 < 2; ks2++) {
        uint ah0, ah1, ah2, ah3, al0, al1, al2, al3;
        sp2(x[ks2][0], ah0, al0);
        sp2(x[ks2][1], ah1, al1);
        sp2(x[ks2][2], ah2, al2);
        sp2(x[ks2][3], ah3, al3);
        const uint kby = (uint)((ksbase + ks2) * 32);
#pragma unroll
        for (int npp = 0; npp < 3; npp++) {
            const uint nbA = (uint)((2 * npp) * 16 * ASTB * 2) + kby;
            const uint nbB = (uint)((2 * npp + 1) * 16 * ASTB * 2) + kby;
            uint hA0, hA1, hA2, hA3, lA0, lA1, lA2, lA3;
            uint hB0, hB1, hB2, hB3, lB0, lB1, lB2, lB3;
            LDSM4(hA0, hA1, hA2, hA3, bB + boff4 + nbA);
            LDSM4(lA0, lA1, lA2, lA3, bB + BSPL + boff4 + nbA);
            LDSM4(hB0, hB1, hB2, hB3, bB + boff4 + nbB);
            LDSM4(lB0, lB1, lB2, lB3, bB + BSPL + boff4 + nbB);
            float* a0 = acc[4 * npp + 0];
            float* a1 = acc[4 * npp + 1];
            float* a2 = acc[4 * npp + 2];
            float* a3 = acc[4 * npp + 3];
            if (npp < 2) {
                mma16816(a0, ah0, ah1, ah2, ah3, hA0, hA1);
                mma16816(a1, ah0, ah1, ah2, ah3, hA2, hA3);
                mma16816(a2, ah0, ah1, ah2, ah3, hB0, hB1);
                mma16816(a3, ah0, ah1, ah2, ah3, hB2, hB3);
                mma16816(a0, ah0, ah1, ah2, ah3, lA0, lA1);
                mma16816(a1, ah0, ah1, ah2, ah3, lA2, lA3);
                mma16816(a2, ah0, ah1, ah2, ah3, lB0, lB1);
                mma16816(a3, ah0, ah1, ah2, ah3, lB2, lB3);
                mma16816(a0, al0, al1, al2, al3, hA0, hA1);
                mma16816(a1, al0, al1, al2, al3, hA2, hA3);
                mma16816(a2, al0, al1, al2, al3, hB0, hB1);
                mma16816(a3, al0, al1, al2, al3, hB2, hB3);
            } else {
                const uint nb12 = (uint)(12 * 8 * ASTB * 2) + kby;
                uint h20, h21, l20, l21;
                LDSM2(h20, h21, bB + boff2 + nb12);
                LDSM2(l20, l21, bB + BSPL + boff2 + nb12);
                float* a4 = acc[12];
                mma16816(a0, ah0, ah1, ah2, ah3, hA0, hA1);
                mma16816(a1, ah0, ah1, ah2, ah3, hA2, hA3);
                mma16816(a2, ah0, ah1, ah2, ah3, hB0, hB1);
                mma16816(a3, ah0, ah1, ah2, ah3, hB2, hB3);
                mma16816(a4, ah0, ah1, ah2, ah3, h20, h21);
                mma16816(a0, ah0, ah1, ah2, ah3, lA0, lA1);
                mma16816(a1, ah0, ah1, ah2, ah3, lA2, lA3);
                mma16816(a2, ah0, ah1, ah2, ah3, lB0, lB1);
                mma16816(a3, ah0, ah1, ah2, ah3, lB2, lB3);
                mma16816(a4, ah0, ah1, ah2, ah3, l20, l21);
                mma16816(a0, al0, al1, al2, al3, hA0, hA1);
                mma16816(a1, al0, al1, al2, al3, hA2, hA3);
                mma16816(a2, al0, al1, al2, al3, hB0, hB1);
                mma16816(a3, al0, al1, al2, al3, hB2, hB3);
                mma16816(a4, al0, al1, al2, al3, h20, h21);
            }
        }
    }
}

template <int STAGE>
__device__ __forceinline__ void gemm_body(const float* __restrict__ se,
                                          const float* __restrict__ mem,
                                          const float* __restrict__ raw,
                                          const float* __restrict__ bias,
                                          float* __restrict__ dout,
                                          int rows)
{
    constexpr int NC = (STAGE == 0) ? 2 : (STAGE == 1 ? 4 : 5);
    constexpr int CBASE = (STAGE == 0) ? 0 : (STAGE == 1 ? 2 : 6);
    extern __shared__ __align__(16) char smc[];
    float* bias_s = (float*)(smc + OFF_BIAS);
    const uint smb = (uint)__cvta_generic_to_shared(smc);
    const int tid = threadIdx.x;
    const int wid = tid >> 5;
    const int lane = tid & 31;
    const int row0 = blockIdx.x * MT;

    if (tid < 104) bias_s[tid] = (tid < HID) ? bias[tid] : 0.0f;

    float acc[13][4];
#pragma unroll
    for (int nt = 0; nt < 13; nt++)
#pragma unroll
        for (int j = 0; j < 4; j++) acc[nt][j] = 0.0f;

    const uint boff2 = (uint)(((lane & 7) * ASTB + ((lane >> 3) & 1) * 8) * 2);
    const uint nrow4 = (uint)((lane & 7) | ((lane >> 1) & 8));
    const uint boff4 = (uint)((nrow4 * ASTB + ((lane >> 3) & 1) * 8) * 2);
    const char* bsrc = (const char*)&g_Bimg[CBASE][0][0];

#pragma unroll
    for (int it = 0; it < 8; it++) {
        int idx = tid + it * 256;
        if (idx < BCHK / 16) cpa16(smb + (uint)(idx * 16), bsrc + idx * 16);
    }
    asm volatile("cp.async.commit_group;");

    const int r_lo = row0 + wid * 16 + (lane >> 2);
    const int r_hi = r_lo + 8;
    int buf = 0;

    float2 xa[2][4], xn[2][4];
    loadA2<STAGE>(xa, se, mem, raw, r_lo, r_hi, 0, 0, lane, rows);

#pragma unroll
    for (int c = 0; c < NC; c++) {
        if (c + 1 < NC) {
            const char* src = bsrc + (c + 1) * BCHK;
            const uint dst = smb + (uint)((buf ^ 1) * BCHK);
#pragma unroll
            for (int it = 0; it < 8; it++) {
                int idx = tid + it * 256;
                if (idx < BCHK / 16) cpa16(dst + (uint)(idx * 16), src + idx * 16);
            }
            asm volatile("cp.async.commit_group;");
            asm volatile("cp.async.wait_group 1;" ::: "memory");
        } else {
            asm volatile("cp.async.wait_group 0;" ::: "memory");
        }
        __syncthreads();

        const uint bB = smb + (uint)(buf * BCHK);

        // prefetch second half of this chunk's A, run first half
        loadA2<STAGE>(xn, se, mem, raw, r_lo, r_hi, c, 1, lane, rows);
        mma_group(acc, xa, bB, boff4, boff2, 0);
#pragma unroll
        for (int j2 = 0; j2 < 2; j2++)
#pragma unroll
            for (int j = 0; j < 4; j++) xa[j2][j] = xn[j2][j];

        // prefetch next chunk's first half, run second half
        if (c + 1 < NC)
            loadA2<STAGE>(xn, se, mem, raw, r_lo, r_hi, c + 1, 0, lane, rows);
        mma_group(acc, xa, bB, boff4, boff2, 2);
        if (c + 1 < NC) {
#pragma unroll
            for (int j2 = 0; j2 < 2; j2++)
#pragma unroll
                for (int j = 0; j < 4; j++) xa[j2][j] = xn[j2][j];
        }

        __syncthreads();
        buf ^= 1;
    }

    // ---- epilogue ----
    const int g = lane >> 2, tg = lane & 3;
    const int r0 = row0 + wid * 16 + g;
    const int r1 = r0 + 8;
#pragma unroll
    for (int nt = 0; nt < 13; nt++) {
        const int n0 = nt * 8 + tg * 2;
        if (n0 >= HID) continue;
        const float bz0 = bias_s[n0], bz1 = bias_s[n0 + 1];
#pragma unroll
        for (int half = 0; half < 2; half++) {
            const int rr = half ? r1 : r0;
            if (rr >= rows) continue;
            float z0 = acc[nt][half * 2]     + bz0;
            float z1 = acc[nt][half * 2 + 1] + bz1;
            const int off = rr * HID + n0;
            float2 o;
            if (STAGE < 2) {
                o.x = tanhf(z0); o.y = tanhf(z1);
                float* dst = (STAGE == 0) ? g_m4 : g_s4;
                *(float2*)&dst[off] = o;
            } else {
                float2 sev = *(const float2*)&se[off];
                float2 smv = *(const float2*)&g_sm[off];
                o.x = fmaf(sigf(z0), smv.x - sev.x, sev.x);
                o.y = fmaf(sigf(z1), smv.y - sev.y, sev.y);
                *(float2*)&dout[off] = o;
            }
        }
    }
}

__global__ __launch_bounds__(256, 2)
void gemm01(const float* __restrict__ se, const float* __restrict__ mem,
            const float* __restrict__ raw,
            const float* __restrict__ b_mem, const float* __restrict__ b_sub,
            int rows)
{
    if (blockIdx.y == 0) gemm_body<0>(se, mem, raw, b_mem, nullptr, rows);
    else                 gemm_body<1>(se, mem, raw, b_sub, nullptr, rows);
}

__global__ __launch_bounds__(256, 2)
void gemm2(const float* __restrict__ se, const float* __restrict__ mem,
           const float* __restrict__ raw, const float* __restrict__ b_gate,
           float* __restrict__ dout, int rows)
{
    gemm_body<2>(se, mem, raw, b_gate, dout, rows);
}

// ---------------------------------------------------------------------------
// Attention: one warp per batch, 8 per CTA; LDS.128 score loop.
// ---------------------------------------------------------------------------
__global__ __launch_bounds__(256)
void attn_kernel(const float* __restrict__ memory,
                 const int* __restrict__ sub_len,
                 int B)
{
    __shared__ __align__(16) float s4s[8][500];
    __shared__ __align__(16) float m4s[8][500];
    __shared__ float atts[8][25];
    __shared__ __align__(16) ull attd[8][25];

    const int w = threadIdx.x >> 5;
    const int lane = threadIdx.x & 31;
    const int b = blockIdx.x * 8 + w;
    if (b >= B) return;

    for (int i = lane; i < 125; i += 32) {
        *(float4*)&s4s[w][4 * i] = *(const float4*)&g_s4[b * 500 + 4 * i];
        *(float4*)&m4s[w][4 * i] = *(const float4*)&g_m4[b * 500 + 4 * i];
    }
    __syncwarp();

    if (lane < 25) {
        const int q = lane / 5, kk = lane % 5;
        float a = 0.0f;
#pragma unroll
        for (int j = 0; j < 25; j++) {
            float4 sv = *(const float4*)&s4s[w][q * 100 + 4 * j];
            float4 mv = *(const float4*)&m4s[w][kk * 100 + 4 * j];
            a += sv.x * mv.x + sv.y * mv.y + sv.z * mv.z + sv.w * mv.w;
        }
        atts[w][lane] = a;
    }
    __syncwarp();

    if (lane < 5) {
        const int q = lane;
        const int len = sub_len[b];
        float a[5];
#pragma unroll
        for (int i = 0; i < 5; i++) a[i] = atts[w][q * 5 + i];
        float m = a[0];
#pragma unroll
        for (int i = 1; i < 5; i++) m = fmaxf(m, a[i]);
        float e[5], s = 0.0f;
#pragma unroll
        for (int i = 0; i < 5; i++) { e[i] = __expf(a[i] - m); s += e[i]; }
        const float inv = (q < len) ? (1.0f / s) : 0.0f;
#pragma unroll
        for (int i = 0; i < 5; i++) {
            float r = e[i] * inv;
            attd[w][q * 5 + i] = pack2(r, r);
        }
    }
    __syncwarp();

    if (lane < 25) {
        const int c0 = 4 * lane;
        ull acc[5][2];
#pragma unroll
        for (int q = 0; q < 5; q++) { acc[q][0] = 0ull; acc[q][1] = 0ull; }
#pragma unroll
        for (int kk = 0; kk < 5; kk++) {
            ulonglong2 mv = *(const ulonglong2*)&memory[b * 500 + kk * 100 + c0];
#pragma unroll
            for (int q = 0; q < 5; q++) {
                ull ad = attd[w][q * 5 + kk];
                acc[q][0] = fma2(ad, mv.x, acc[q][0]);
                acc[q][1] = fma2(ad, mv.y, acc[q][1]);
            }
        }
#pragma unroll
        for (int q = 0; q < 5; q++) {
            float2 a01 = unpack2(acc[q][0]);
            float2 a23 = unpack2(acc[q][1]);
            float4 o; o.x = a01.x; o.y = a01.y; o.z = a23.x; o.w = a23.y;
            *(float4*)&g_sm[b * 500 + q * 100 + c0] = o;
        }
    }
}

// ---------------------------------------------------------------------------
extern "C" void kernel_launch(void* const* d_in, const int* in_sizes, int n_in,
                              void* d_out, int out_size)
{
    const float* sub_emb = (const float*)d_in[0];
    const float* memory  = (const float*)d_in[1];
    const int*   sub_len = (const int*)d_in[2];
    const float* raw     = (const float*)d_in[3];
    const float* W_mem   = (const float*)d_in[4];
    const float* b_mem   = (const float*)d_in[5];
    const float* W_sub   = (const float*)d_in[6];
    const float* b_sub   = (const float*)d_in[7];
    const float* W_gate  = (const float*)d_in[8];
    const float* b_gate  = (const float*)d_in[9];
    float* out = (float*)d_out;
    const int B = in_sizes[2];
    const int rows = B * 5;
    const int tiles = (rows + MT - 1) / MT;

    cudaFuncSetAttribute(gemm01, cudaFuncAttributeMaxDynamicSharedMemorySize, GSMEM);
    cudaFuncSetAttribute(gemm2,  cudaFuncAttributeMaxDynamicSharedMemorySize, GSMEM);

    prep_kernel<<<(11 * 104 * KCH + 255) / 256, 256>>>(W_mem, W_sub, W_gate);
    gemm01<<<dim3(tiles, 2), 256, GSMEM>>>(sub_emb, memory, raw, b_mem, b_sub, rows);
    attn_kernel<<<(B + 7) / 8, 256>>>(memory, sub_len, B);
    gemm2<<<tiles, 256, GSMEM>>>(sub_emb, memory, raw, b_gate, out, rows);
}